// round 6
// baseline (speedup 1.0000x reference)
#include <cuda_runtime.h>
#include <cuda_bf16.h>

#define NB   16
#define NA   8400
#define NCLS 80
#define PRE  1000
#define KEEP 100

// ---------------- global scratch (no allocations allowed) ----------------
static __device__ float4   g_box[NB * NA];
static __device__ float    g_score[NB * NA];
static __device__ unsigned g_key[NB * NA];
static __device__ int      g_label[NB * NA];

static __device__ float4   g_rawbox_c[NB * PRE];
static __device__ float4   g_offbox_c[NB * PRE];
static __device__ float    g_area_c[NB * PRE];
static __device__ float    g_score_c[NB * PRE];
static __device__ int      g_label_c[NB * PRE];

// ---------------- XLA-exact sigmoid -------------------------------------
// XLA logistic expander: logistic(x) = 0.5 + 0.5 * tanh(0.5 * x)
// XLA fast-tanh (xla/service/llvm_ir/math_ops.cc): clamp [-9,9], rational
// poly, tanh(x)=x for |x| < 0.0004. All ops round-to-nearest, no FMA.
__device__ __forceinline__ float xla_fast_tanh(float x) {
    float ax = fabsf(x);
    float xc = fminf(fmaxf(x, -9.0f), 9.0f);
    float x2 = __fmul_rn(xc, xc);
    float num = -2.76076847742355e-16f;
    num = __fadd_rn(__fmul_rn(x2, num), 2.00018790482477e-13f);
    num = __fadd_rn(__fmul_rn(x2, num), -8.60467152213735e-11f);
    num = __fadd_rn(__fmul_rn(x2, num), 5.12229709037114e-08f);
    num = __fadd_rn(__fmul_rn(x2, num), 1.48572235717979e-05f);
    num = __fadd_rn(__fmul_rn(x2, num), 6.37261928875436e-04f);
    num = __fadd_rn(__fmul_rn(x2, num), 4.89352455891786e-03f);
    num = __fmul_rn(xc, num);
    float den = 1.19825839466702e-06f;
    den = __fadd_rn(__fmul_rn(x2, den), 1.18534705686654e-04f);
    den = __fadd_rn(__fmul_rn(x2, den), 2.26843463243900e-03f);
    den = __fadd_rn(__fmul_rn(x2, den), 4.89352518554385e-03f);
    float r = __fdiv_rn(num, den);
    return (ax < 0.0004f) ? x : r;
}
__device__ __forceinline__ float xla_sigmoid(float x) {
    return __fadd_rn(0.5f, __fmul_rn(0.5f, xla_fast_tanh(__fmul_rn(0.5f, x))));
}

// ---------------- stage A: score/label/decode per anchor ----------------
__global__ void k_score(const float* __restrict__ cls0, const float* __restrict__ cls1,
                        const float* __restrict__ cls2, const float* __restrict__ box0,
                        const float* __restrict__ box1, const float* __restrict__ box2) {
    int a = blockIdx.x * blockDim.x + threadIdx.x;
    int b = blockIdx.y;
    if (a >= NA) return;

    const float* cp; const float* bp;
    int hw, W, local; float sf;
    if (a < 6400)      { local = a;        hw = 6400; W = 80; sf = 8.0f;
                         cp = cls0 + (size_t)b * NCLS * 6400; bp = box0 + (size_t)b * 4 * 6400; }
    else if (a < 8000) { local = a - 6400; hw = 1600; W = 40; sf = 16.0f;
                         cp = cls1 + (size_t)b * NCLS * 1600; bp = box1 + (size_t)b * 4 * 1600; }
    else               { local = a - 8000; hw = 400;  W = 20; sf = 32.0f;
                         cp = cls2 + (size_t)b * NCLS * 400;  bp = box2 + (size_t)b * 4 * 400; }

    // max over class sigmoids; first-occurrence argmax (matches jnp)
    float best = -1.0f; int lab = 0;
    #pragma unroll 8
    for (int c = 0; c < NCLS; c++) {
        float sc = xla_sigmoid(cp[(size_t)c * hw + local]);
        if (sc > best) { best = sc; lab = c; }
    }
    bool valid = best > 0.25f;
    float masked = valid ? best : 0.0f;

    int gi = b * NA + a;
    g_score[gi] = masked;
    g_key[gi]   = __float_as_uint(masked) | 0x80000000u;  // order-preserving (f>=0)
    g_label[gi] = lab;

    float px = __fmul_rn((float)(local % W), sf);
    float py = __fmul_rn((float)(local / W), sf);
    float d0 = __fmul_rn(bp[local], sf);
    float d1 = __fmul_rn(bp[hw + local], sf);
    float d2 = __fmul_rn(bp[2 * hw + local], sf);
    float d3 = __fmul_rn(bp[3 * hw + local], sf);
    g_box[gi] = make_float4(__fsub_rn(px, d0), __fsub_rn(py, d1),
                            __fadd_rn(px, d2), __fadd_rn(py, d3));
}

// ---------------- stage B: exact stable top-1000 per batch --------------
// Binary-search the 1000th key value over a shared key cache, gather the
// >= threshold candidates from global, bitonic-sort (key desc, idx asc).
__global__ void __launch_bounds__(1024) k_select() {
    __shared__ unsigned long long smemB[4200];             // 33600 B, aliased
    unsigned*            skey  = (unsigned*)smemB;          // [8400] search phase
    unsigned long long*  ssort = smemB;                     // [2048] sort phase
    __shared__ int s_cnt;
    __shared__ int s_n;

    int b = blockIdx.x, tid = threadIdx.x;

    for (int i = tid; i < NA; i += 1024) skey[i] = g_key[b * NA + i];
    __syncthreads();

    // invariant: count(key >= lo) >= PRE.  find largest such lo.
    unsigned lo = 0u, hi = 0xFFFFFFFFu;
    while (lo < hi) {
        unsigned mid = lo + ((hi - lo) >> 1) + 1u;
        if (tid == 0) s_cnt = 0;
        __syncthreads();
        int c = 0;
        for (int i = tid; i < NA; i += 1024) c += (skey[i] >= mid);
        for (int d = 16; d; d >>= 1) c += __shfl_down_sync(0xffffffffu, c, d);
        if ((tid & 31) == 0 && c) atomicAdd(&s_cnt, c);
        __syncthreads();
        int total = s_cnt;
        __syncthreads();
        if (total >= PRE) lo = mid; else hi = mid - 1u;
    }
    unsigned v = lo;
    __syncthreads();  // done reading skey before ssort overwrites it

    if (tid == 0) s_n = 0;
    __syncthreads();
    for (int i = tid; i < NA; i += 1024) {
        unsigned k = g_key[b * NA + i];
        if (k >= v) {
            int pos = atomicAdd(&s_n, 1);
            if (pos < 2048)
                ssort[pos] = ((unsigned long long)k << 32) | (unsigned)(~i);
        }
    }
    __syncthreads();
    int n = s_n; if (n > 2048) n = 2048;          // n >= PRE by construction
    const int npow = 2048;
    for (int i = tid; i < npow; i += 1024)
        if (i >= n) ssort[i] = 0ULL;
    __syncthreads();

    // bitonic sort, descending (stable top-k order: key desc, idx asc via ~i)
    for (int k = 2; k <= npow; k <<= 1) {
        for (int j = k >> 1; j > 0; j >>= 1) {
            for (int i = tid; i < npow; i += 1024) {
                int ixj = i ^ j;
                if (ixj > i) {
                    unsigned long long x = ssort[i], y = ssort[ixj];
                    bool desc = ((i & k) == 0);
                    if ((x < y) == desc) { ssort[i] = y; ssort[ixj] = x; }
                }
            }
            __syncthreads();
        }
    }

    if (tid < PRE) {
        unsigned long long e = ssort[tid];
        int idx = (int)(~(unsigned)e);
        int gi = b * NA + idx;
        float sc = g_score[gi];
        int lab = g_label[gi];
        float4 bx = g_box[gi];
        int o = b * PRE + tid;
        g_rawbox_c[o] = bx;
        g_score_c[o]  = sc;
        g_label_c[o]  = lab;
        float off = __fmul_rn((float)lab, 8192.0f);
        float4 ob = make_float4(__fadd_rn(bx.x, off), __fadd_rn(bx.y, off),
                                __fadd_rn(bx.z, off), __fadd_rn(bx.w, off));
        g_offbox_c[o] = ob;
        g_area_c[o] = __fmul_rn(fmaxf(__fsub_rn(ob.z, ob.x), 0.0f),
                                fmaxf(__fsub_rn(ob.w, ob.y), 0.0f));
    }
}

// ---------------- stage C: per-class greedy NMS + top-100 emit ----------
// Cross-class IoU is exactly 0 (8192-per-class offset >> box extent), so the
// reference's sequential scan decomposes into independent per-class greedy
// NMS; within a class, restricting suppression to j>i is equivalent.
__global__ void __launch_bounds__(1024) k_nms(float* __restrict__ dout) {
    __shared__ float4 sbox[PRE];
    __shared__ float  sarea[PRE];
    __shared__ int    slabel[PRE];
    __shared__ int    slist[PRE];
    __shared__ int    sstart[NCLS + 1];
    __shared__ int    scnt[NCLS];
    __shared__ unsigned char ssupp[PRE];
    __shared__ int    swarp[32];

    int b = blockIdx.x, tid = threadIdx.x;
    int wid = tid >> 5, lane = tid & 31;

    for (int i = tid; i < PRE; i += 1024) {
        int o = b * PRE + i;
        sbox[i]   = g_offbox_c[o];
        sarea[i]  = g_area_c[o];
        slabel[i] = g_label_c[o];
        ssupp[i]  = (g_score_c[o] > 0.25f) ? 0 : 1;   // invalid = pre-suppressed
    }
    __syncthreads();

    // deterministic per-class candidate lists (position-ascending order)
    if (tid < NCLS) {
        int cnt = 0;
        for (int i = 0; i < PRE; i++) cnt += (slabel[i] == tid);
        scnt[tid] = cnt;
    }
    __syncthreads();
    if (tid == 0) {
        int acc = 0;
        for (int c = 0; c < NCLS; c++) { sstart[c] = acc; acc += scnt[c]; }
        sstart[NCLS] = acc;
    }
    __syncthreads();
    if (tid < NCLS) {
        int p = sstart[tid];
        for (int i = 0; i < PRE; i++)
            if (slabel[i] == tid) slist[p++] = i;
    }
    __syncthreads();

    // one warp per class; greedy NMS with reference-exact IoU arithmetic
    for (int c = wid; c < NCLS; c += 32) {
        int st = sstart[c], ni = sstart[c + 1] - st;
        for (int ii = 0; ii < ni; ii++) {
            __syncwarp();
            int idx_i = slist[st + ii];
            if (ssupp[idx_i]) continue;      // all lanes read same byte -> converged
            float4 bi = sbox[idx_i];
            float  ai = sarea[idx_i];
            for (int jj = ii + 1 + lane; jj < ni; jj += 32) {
                int idx_j = slist[st + jj];
                float4 bj = sbox[idx_j];
                float ltx = fmaxf(bi.x, bj.x), lty = fmaxf(bi.y, bj.y);
                float rbx = fminf(bi.z, bj.z), rby = fminf(bi.w, bj.w);
                float w = fmaxf(__fsub_rn(rbx, ltx), 0.0f);
                float h = fmaxf(__fsub_rn(rby, lty), 0.0f);
                float inter = __fmul_rn(w, h);
                float den = fmaxf(__fsub_rn(__fadd_rn(ai, sarea[idx_j]), inter), 1e-6f);
                if (__fdiv_rn(inter, den) > 0.65f) ssupp[idx_j] = 1;
            }
        }
        __syncwarp();
    }
    __syncthreads();

    // emit: kept entries keep sorted position order; zero-score fills follow
    // in ascending position order (exact top_k tie semantics, no re-sort).
    bool keep = (tid < PRE) ? (ssupp[tid] == 0) : false;
    unsigned bal = __ballot_sync(0xffffffffu, keep);
    int before_in_warp = __popc(bal & ((1u << lane) - 1u));
    if (lane == 0) swarp[wid] = __popc(bal);
    __syncthreads();
    if (tid < 32) {
        int v = swarp[tid];
        for (int d = 1; d < 32; d <<= 1) {
            int t = __shfl_up_sync(0xffffffffu, v, d);
            if (lane >= d) v += t;
        }
        swarp[tid] = v;                       // inclusive scan of warp counts
    }
    __syncthreads();
    int rank = ((wid == 0) ? 0 : swarp[wid - 1]) + before_in_warp;  // keeps before tid
    int K = swarp[31];

    if (tid < PRE) {
        int slot = keep ? rank : (K + (tid - rank));
        if (slot < KEEP) {
            int o = b * PRE + tid;
            float4 rb = g_rawbox_c[o];
            float sc = keep ? g_score_c[o] : 0.0f;
            int lab = g_label_c[o];
            float* dd = dout + (size_t)b * KEEP * 5 + (size_t)slot * 5;
            dd[0] = rb.x; dd[1] = rb.y; dd[2] = rb.z; dd[3] = rb.w; dd[4] = sc;
            dout[(size_t)NB * KEEP * 5 + b * KEEP + slot] = (float)lab;
        }
    }
}

extern "C" void kernel_launch(void* const* d_in, const int* in_sizes, int n_in,
                              void* d_out, int out_size) {
    const float* cls0 = (const float*)d_in[0];
    const float* cls1 = (const float*)d_in[1];
    const float* cls2 = (const float*)d_in[2];
    const float* box0 = (const float*)d_in[3];
    const float* box1 = (const float*)d_in[4];
    const float* box2 = (const float*)d_in[5];
    float* out = (float*)d_out;

    dim3 gA((NA + 127) / 128, NB);
    k_score<<<gA, 128>>>(cls0, cls1, cls2, box0, box1, box2);
    k_select<<<NB, 1024>>>();
    k_nms<<<NB, 1024>>>(out);
}

// round 7
// speedup vs baseline: 1.6117x; 1.6117x over previous
#include <cuda_runtime.h>
#include <cuda_bf16.h>

#define NB   16
#define NA   8400
#define NCLS 80
#define PRE  1000
#define KEEP 100

// ---------------- global scratch (stage-A outputs only) ------------------
static __device__ float4   g_box[NB * NA];
static __device__ float    g_score[NB * NA];
static __device__ unsigned g_key[NB * NA];
static __device__ int      g_label[NB * NA];

// ---------------- XLA-exact sigmoid -------------------------------------
// XLA logistic expander: logistic(x) = 0.5 + 0.5 * tanh(0.5 * x)
// XLA fast-tanh: clamp [-9,9], rational poly, identity for |x| < 0.0004.
__device__ __forceinline__ float xla_fast_tanh(float x) {
    float ax = fabsf(x);
    float xc = fminf(fmaxf(x, -9.0f), 9.0f);
    float x2 = __fmul_rn(xc, xc);
    float num = -2.76076847742355e-16f;
    num = __fadd_rn(__fmul_rn(x2, num), 2.00018790482477e-13f);
    num = __fadd_rn(__fmul_rn(x2, num), -8.60467152213735e-11f);
    num = __fadd_rn(__fmul_rn(x2, num), 5.12229709037114e-08f);
    num = __fadd_rn(__fmul_rn(x2, num), 1.48572235717979e-05f);
    num = __fadd_rn(__fmul_rn(x2, num), 6.37261928875436e-04f);
    num = __fadd_rn(__fmul_rn(x2, num), 4.89352455891786e-03f);
    num = __fmul_rn(xc, num);
    float den = 1.19825839466702e-06f;
    den = __fadd_rn(__fmul_rn(x2, den), 1.18534705686654e-04f);
    den = __fadd_rn(__fmul_rn(x2, den), 2.26843463243900e-03f);
    den = __fadd_rn(__fmul_rn(x2, den), 4.89352518554385e-03f);
    float r = __fdiv_rn(num, den);
    return (ax < 0.0004f) ? x : r;
}
__device__ __forceinline__ float xla_sigmoid(float x) {
    return __fadd_rn(0.5f, __fmul_rn(0.5f, xla_fast_tanh(__fmul_rn(0.5f, x))));
}

// ---------------- stage A: top-2 logit tracking, sigmoid only at the end
// max(sigmoid) == sigmoid(max logit) when the runner-up logit is >= 1e-3
// below (slope*delta >= 4e-6 over attainable logits, vs ~6e-8 output ulp).
// Near-ties (<2% of anchors) evaluate both sigmoids with reference
// first-index tie-breaking.
__global__ void __launch_bounds__(256) k_score(
        const float* __restrict__ cls0, const float* __restrict__ cls1,
        const float* __restrict__ cls2, const float* __restrict__ box0,
        const float* __restrict__ box1, const float* __restrict__ box2) {
    int p = blockIdx.x * blockDim.x + threadIdx.x;   // group of 4 anchors
    int b = blockIdx.y;
    if (p >= NA / 4) return;

    const float4* cp4; const float4* bp4;
    int hw4, W, lp, abase; float sf;
    if (p < 1600)      { lp = p;        hw4 = 1600; W = 80; sf = 8.0f;  abase = 0;
                         cp4 = (const float4*)cls0 + (size_t)b * NCLS * 1600;
                         bp4 = (const float4*)box0 + (size_t)b * 4 * 1600; }
    else if (p < 2000) { lp = p - 1600; hw4 = 400;  W = 40; sf = 16.0f; abase = 6400;
                         cp4 = (const float4*)cls1 + (size_t)b * NCLS * 400;
                         bp4 = (const float4*)box1 + (size_t)b * 4 * 400; }
    else               { lp = p - 2000; hw4 = 100;  W = 20; sf = 32.0f; abase = 8000;
                         cp4 = (const float4*)cls2 + (size_t)b * NCLS * 100;
                         bp4 = (const float4*)box2 + (size_t)b * 4 * 100; }

    float best[4], best2[4];
    int   lab[4],  lab2[4];
    #pragma unroll
    for (int j = 0; j < 4; j++) { best[j] = -1e30f; best2[j] = -1e30f; lab[j] = 0; lab2[j] = 0; }

    #pragma unroll 4
    for (int c = 0; c < NCLS; c++) {
        float4 v = cp4[(size_t)c * hw4 + lp];
        float xs[4] = {v.x, v.y, v.z, v.w};
        #pragma unroll
        for (int j = 0; j < 4; j++) {
            float x = xs[j];
            if (x > best[j])       { best2[j] = best[j]; lab2[j] = lab[j]; best[j] = x; lab[j] = c; }
            else if (x > best2[j]) { best2[j] = x; lab2[j] = c; }
        }
    }

    float4 d0 = bp4[lp], d1 = bp4[hw4 + lp], d2 = bp4[2 * hw4 + lp], d3 = bp4[3 * hw4 + lp];
    float dd0[4] = {d0.x, d0.y, d0.z, d0.w};
    float dd1[4] = {d1.x, d1.y, d1.z, d1.w};
    float dd2[4] = {d2.x, d2.y, d2.z, d2.w};
    float dd3[4] = {d3.x, d3.y, d3.z, d3.w};

    float score4[4]; unsigned key4[4]; int lab4[4];
    int base4 = (b * NA + abase) / 4 + lp;

    #pragma unroll
    for (int j = 0; j < 4; j++) {
        float s1 = xla_sigmoid(best[j]);
        float sc = s1; int lb = lab[j];
        if (__fsub_rn(best[j], best2[j]) < 1e-3f) {       // rare near-tie
            float s2 = xla_sigmoid(best2[j]);
            if (s2 > s1 || (s2 == s1 && lab2[j] < lb)) { sc = s2; lb = lab2[j]; }
        }
        float masked = (sc > 0.25f) ? sc : 0.0f;
        score4[j] = masked;
        key4[j]   = __float_as_uint(masked) | 0x80000000u;
        lab4[j]   = lb;

        int localj = lp * 4 + j;
        float px = __fmul_rn((float)(localj % W), sf);
        float py = __fmul_rn((float)(localj / W), sf);
        float e0 = __fmul_rn(dd0[j], sf);
        float e1 = __fmul_rn(dd1[j], sf);
        float e2 = __fmul_rn(dd2[j], sf);
        float e3 = __fmul_rn(dd3[j], sf);
        g_box[base4 * 4 + j] = make_float4(__fsub_rn(px, e0), __fsub_rn(py, e1),
                                           __fadd_rn(px, e2), __fadd_rn(py, e3));
    }
    ((float4*)g_score)[base4] = make_float4(score4[0], score4[1], score4[2], score4[3]);
    ((uint4*)g_key)[base4]    = make_uint4(key4[0], key4[1], key4[2], key4[3]);
    ((int4*)g_label)[base4]   = make_int4(lab4[0], lab4[1], lab4[2], lab4[3]);
}

// ---------------- fused stage B+C: top-1000 select + NMS + emit ----------
#define SB_SAREA  16000
#define SB_SLABEL 20000
#define SB_SLIST  24000
#define SB_SSUPP  28000

__global__ void __launch_bounds__(1024) k_sel_nms(float* __restrict__ dout) {
    __shared__ __align__(16) char sbuf[33600];
    unsigned*           skey  = (unsigned*)sbuf;             // [8400] search
    unsigned long long* ssort = (unsigned long long*)sbuf;   // [2048] sort
    float4*        sbox   = (float4*)sbuf;                   // [1000] nms
    float*         sarea  = (float*)(sbuf + SB_SAREA);
    int*           slabel = (int*)(sbuf + SB_SLABEL);
    int*           slist  = (int*)(sbuf + SB_SLIST);
    unsigned char* ssupp  = (unsigned char*)(sbuf + SB_SSUPP);

    __shared__ int s_cnt[32];
    __shared__ int s_n;
    __shared__ int sstart[NCLS + 1];
    __shared__ int scnt_[NCLS];
    __shared__ int swarp[32];

    int b = blockIdx.x, tid = threadIdx.x;
    int wid = tid >> 5, lane = tid & 31;

    for (int i = tid; i < NA; i += 1024) skey[i] = g_key[b * NA + i];
    if (tid < 32) s_cnt[tid] = 0;
    if (tid == 0) s_n = 0;
    __syncthreads();

    // exact threshold: largest v with count(key >= v) >= PRE.
    // one barrier per iteration via iteration-indexed count slots.
    unsigned lo = 0x80000000u, hi = 0xBF7FFFFFu;
    int it = 0;
    while (lo < hi) {
        unsigned mid = lo + ((hi - lo) >> 1) + 1u;
        int c = 0;
        for (int i = tid; i < NA; i += 1024) c += (skey[i] >= mid);
        for (int d = 16; d; d >>= 1) c += __shfl_down_sync(0xffffffffu, c, d);
        if (lane == 0 && c) atomicAdd(&s_cnt[it], c);
        __syncthreads();
        if (s_cnt[it] >= PRE) lo = mid; else hi = mid - 1u;
        it++;
    }
    unsigned v = lo;
    __syncthreads();                     // done with skey before ssort aliases it

    // gather candidates from global (L2-hot); write aliased sort buffer
    for (int i = tid; i < NA; i += 1024) {
        unsigned k = g_key[b * NA + i];
        if (k >= v) {
            int pos = atomicAdd(&s_n, 1);
            if (pos < 2048)
                ssort[pos] = ((unsigned long long)k << 32) | (unsigned)(~i);
        }
    }
    __syncthreads();
    int n = s_n; if (n > 2048) n = 2048;         // n >= PRE; exact threshold => n ~ 1000
    int npow = (n <= 1024) ? 1024 : 2048;
    for (int i = tid; i < npow; i += 1024)
        if (i >= n) ssort[i] = 0ULL;
    __syncthreads();

    // bitonic sort descending (key desc, idx asc via ~i)
    for (int k = 2; k <= npow; k <<= 1) {
        for (int j = k >> 1; j > 0; j >>= 1) {
            for (int i = tid; i < npow; i += 1024) {
                int ixj = i ^ j;
                if (ixj > i) {
                    unsigned long long x = ssort[i], y = ssort[ixj];
                    bool desc = ((i & k) == 0);
                    if ((x < y) == desc) { ssort[i] = y; ssort[ixj] = x; }
                }
            }
            __syncthreads();
        }
    }

    // extract own candidate into registers, then repurpose sbuf for NMS
    float4 myraw = make_float4(0, 0, 0, 0);
    float  mysc = 0.0f; int mylab = 0;
    float4 myoff = myraw; float myarea = 0.0f;
    if (tid < PRE) {
        unsigned long long e = ssort[tid];
        int idx = (int)(~(unsigned)e);
        int gi = b * NA + idx;
        myraw = g_box[gi];
        mysc  = g_score[gi];
        mylab = g_label[gi];
        float off = __fmul_rn((float)mylab, 8192.0f);
        myoff = make_float4(__fadd_rn(myraw.x, off), __fadd_rn(myraw.y, off),
                            __fadd_rn(myraw.z, off), __fadd_rn(myraw.w, off));
        myarea = __fmul_rn(fmaxf(__fsub_rn(myoff.z, myoff.x), 0.0f),
                           fmaxf(__fsub_rn(myoff.w, myoff.y), 0.0f));
    }
    __syncthreads();                     // everyone done reading ssort
    if (tid < PRE) {
        sbox[tid]   = myoff;
        sarea[tid]  = myarea;
        slabel[tid] = mylab;
        ssupp[tid]  = (mysc > 0.25f) ? 0 : 1;     // invalid = pre-suppressed
    }
    __syncthreads();

    // warp-ballot per-class grouping (order-preserving within class)
    for (int c = wid; c < NCLS; c += 32) {
        int cnt = 0;
        for (int base = 0; base < PRE; base += 32) {
            int i = base + lane;
            bool m = (i < PRE) && (slabel[i] == c);
            cnt += __popc(__ballot_sync(0xffffffffu, m));
        }
        if (lane == 0) scnt_[c] = cnt;
    }
    __syncthreads();
    if (tid == 0) {
        int acc = 0;
        for (int c = 0; c < NCLS; c++) { sstart[c] = acc; acc += scnt_[c]; }
        sstart[NCLS] = acc;
    }
    __syncthreads();
    for (int c = wid; c < NCLS; c += 32) {
        int p = sstart[c];
        for (int base = 0; base < PRE; base += 32) {
            int i = base + lane;
            bool m = (i < PRE) && (slabel[i] == c);
            unsigned bal = __ballot_sync(0xffffffffu, m);
            if (m) slist[p + __popc(bal & ((1u << lane) - 1u))] = i;
            p += __popc(bal);
        }
    }
    __syncthreads();

    // one warp per class; greedy NMS with reference-exact IoU arithmetic.
    // cross-class IoU is exactly 0 (8192 class offset), so classes decouple.
    for (int c = wid; c < NCLS; c += 32) {
        int st = sstart[c], ni = sstart[c + 1] - st;
        for (int ii = 0; ii < ni; ii++) {
            __syncwarp();
            int idx_i = slist[st + ii];
            if (ssupp[idx_i]) continue;
            float4 bi = sbox[idx_i];
            float  ai = sarea[idx_i];
            for (int jj = ii + 1 + lane; jj < ni; jj += 32) {
                int idx_j = slist[st + jj];
                float4 bj = sbox[idx_j];
                float ltx = fmaxf(bi.x, bj.x), lty = fmaxf(bi.y, bj.y);
                float rbx = fminf(bi.z, bj.z), rby = fminf(bi.w, bj.w);
                float w = fmaxf(__fsub_rn(rbx, ltx), 0.0f);
                float h = fmaxf(__fsub_rn(rby, lty), 0.0f);
                float inter = __fmul_rn(w, h);
                float den = fmaxf(__fsub_rn(__fadd_rn(ai, sarea[idx_j]), inter), 1e-6f);
                if (__fdiv_rn(inter, den) > 0.65f) ssupp[idx_j] = 1;
            }
        }
        __syncwarp();
    }
    __syncthreads();

    // emit: kept entries keep sorted order; zero-score fills index-ascending
    bool keep = (tid < PRE) ? (ssupp[tid] == 0) : false;
    unsigned bal = __ballot_sync(0xffffffffu, keep);
    int before_in_warp = __popc(bal & ((1u << lane) - 1u));
    if (lane == 0) swarp[wid] = __popc(bal);
    __syncthreads();
    if (tid < 32) {
        int vv = swarp[tid];
        for (int d = 1; d < 32; d <<= 1) {
            int t = __shfl_up_sync(0xffffffffu, vv, d);
            if (lane >= d) vv += t;
        }
        swarp[tid] = vv;
    }
    __syncthreads();
    int rank = ((wid == 0) ? 0 : swarp[wid - 1]) + before_in_warp;
    int K = swarp[31];

    if (tid < PRE) {
        int slot = keep ? rank : (K + (tid - rank));
        if (slot < KEEP) {
            float* dd = dout + (size_t)b * KEEP * 5 + (size_t)slot * 5;
            float sc = keep ? mysc : 0.0f;
            dd[0] = myraw.x; dd[1] = myraw.y; dd[2] = myraw.z; dd[3] = myraw.w; dd[4] = sc;
            dout[(size_t)NB * KEEP * 5 + b * KEEP + slot] = (float)mylab;
        }
    }
}

extern "C" void kernel_launch(void* const* d_in, const int* in_sizes, int n_in,
                              void* d_out, int out_size) {
    const float* cls0 = (const float*)d_in[0];
    const float* cls1 = (const float*)d_in[1];
    const float* cls2 = (const float*)d_in[2];
    const float* box0 = (const float*)d_in[3];
    const float* box1 = (const float*)d_in[4];
    const float* box2 = (const float*)d_in[5];
    float* out = (float*)d_out;

    dim3 gA((NA / 4 + 255) / 256, NB);
    k_score<<<gA, 256>>>(cls0, cls1, cls2, box0, box1, box2);
    k_sel_nms<<<NB, 1024>>>(out);
}